// round 1
// baseline (speedup 1.0000x reference)
#include <cuda_runtime.h>

#define NNODES 100000
#define NEDGES 1600000
#define F0 128
#define F1 64
#define F2 16

// Scratch (device globals: allocation-free, graph-safe)
__device__ float g_deg [NNODES];
__device__ float g_dinv[NNODES];
__device__ float g_h1  [NNODES * F1];
__device__ float g_agg1[NNODES * F1];
__device__ float g_h2  [NNODES * F2];
__device__ float g_agg2[NNODES * F2];

// ---------------------------------------------------------------------------
// Init: zero aggregation buffers, deg = 1 (self loop)
// ---------------------------------------------------------------------------
__global__ void gcn_init_kernel() {
    int i = blockIdx.x * blockDim.x + threadIdx.x;
    if (i < NNODES * F1) g_agg1[i] = 0.f;
    if (i < NNODES * F2) g_agg2[i] = 0.f;
    if (i < NNODES)      g_deg[i]  = 1.f;
}

// ---------------------------------------------------------------------------
// Degree accumulation over dst, then dinv = rsqrt(deg)
// ---------------------------------------------------------------------------
__global__ void gcn_deg_kernel(const int* __restrict__ dst) {
    int e = blockIdx.x * blockDim.x + threadIdx.x;
    if (e < NEDGES) atomicAdd(&g_deg[dst[e]], 1.0f);
}

__global__ void gcn_dinv_kernel() {
    int i = blockIdx.x * blockDim.x + threadIdx.x;
    if (i < NNODES) g_dinv[i] = rsqrtf(g_deg[i]);
}

// ---------------------------------------------------------------------------
// GEMM1: h1[v,:] = (x[v,:] @ W1) * dinv[v]     [N,128]x[128,64]
// 256 threads/block, 16 rows/block, each thread computes a float4 of outputs.
// ---------------------------------------------------------------------------
#define G1_ROWS 16
__global__ void gcn_gemm1_kernel(const float* __restrict__ x,
                                 const float* __restrict__ W1) {
    __shared__ __align__(16) float Ws[F0 * F1];        // 32 KB
    __shared__ __align__(16) float xs[G1_ROWS][F0];    // 8 KB
    int tid = threadIdx.x;
    for (int i = tid; i < F0 * F1; i += 256) Ws[i] = W1[i];

    int row0 = blockIdx.x * G1_ROWS;
    for (int i = tid; i < G1_ROWS * F0; i += 256) {
        int r = i >> 7, c = i & 127;
        xs[r][c] = x[(row0 + r) * F0 + c];
    }
    __syncthreads();

    int r = tid >> 4;               // 0..15 local row
    int q = (tid & 15) * 4;         // output feature quad
    int v = row0 + r;

    float4 acc = make_float4(0.f, 0.f, 0.f, 0.f);
#pragma unroll 8
    for (int k = 0; k < F0; k++) {
        float  xv = xs[r][k];
        float4 w  = *(const float4*)&Ws[k * F1 + q];
        acc.x += xv * w.x; acc.y += xv * w.y;
        acc.z += xv * w.z; acc.w += xv * w.w;
    }
    float dv = g_dinv[v];
    acc.x *= dv; acc.y *= dv; acc.z *= dv; acc.w *= dv;
    *(float4*)&g_h1[v * F1 + q] = acc;
}

// ---------------------------------------------------------------------------
// Edge scatter layer 1: agg1[dst] += h1[src]   (64 floats = 16 lanes x float4)
// ---------------------------------------------------------------------------
__global__ void gcn_scatter1_kernel(const int* __restrict__ src,
                                    const int* __restrict__ dst) {
    int t = blockIdx.x * blockDim.x + threadIdx.x;
    int e = t >> 4;
    int lane = t & 15;
    if (e >= NEDGES) return;
    int s = src[e], d = dst[e];
    float4 v = *(const float4*)&g_h1[s * F1 + lane * 4];
    float* p = &g_agg1[d * F1 + lane * 4];
    asm volatile("red.global.add.v4.f32 [%0], {%1, %2, %3, %4};"
                 :: "l"(p), "f"(v.x), "f"(v.y), "f"(v.z), "f"(v.w) : "memory");
}

// ---------------------------------------------------------------------------
// Fused layer-2 input: t = leaky_relu(dinv*(agg1+h1) + b1); h2 = (t@W2)*dinv
// 256 threads/block, 16 nodes/block, 16 threads per node (one per out feat).
// ---------------------------------------------------------------------------
__global__ void gcn_layer2_kernel(const float* __restrict__ W2,
                                  const float* __restrict__ b1) {
    __shared__ __align__(16) float W2s[F1 * F2];     // 4 KB
    __shared__ __align__(16) float ts[16][F1];       // 4 KB
    __shared__ float b1s[F1];
    int tid = threadIdx.x;
    for (int i = tid; i < F1 * F2; i += 256) W2s[i] = W2[i];
    if (tid < F1) b1s[tid] = b1[tid];
    __syncthreads();

    int r = tid >> 4;              // local node
    int m = tid & 15;              // output feature
    int v = blockIdx.x * 16 + r;
    float dv = g_dinv[v];

    {   // compute activated row t (4 features per thread)
        int j = m * 4;
        float4 a = *(const float4*)&g_agg1[v * F1 + j];
        float4 h = *(const float4*)&g_h1 [v * F1 + j];
        float4 t;
        t.x = dv * (a.x + h.x) + b1s[j + 0];
        t.y = dv * (a.y + h.y) + b1s[j + 1];
        t.z = dv * (a.z + h.z) + b1s[j + 2];
        t.w = dv * (a.w + h.w) + b1s[j + 3];
        t.x = t.x >= 0.f ? t.x : 0.2f * t.x;
        t.y = t.y >= 0.f ? t.y : 0.2f * t.y;
        t.z = t.z >= 0.f ? t.z : 0.2f * t.z;
        t.w = t.w >= 0.f ? t.w : 0.2f * t.w;
        *(float4*)&ts[r][j] = t;
    }
    __syncthreads();

    float acc = 0.f;
#pragma unroll
    for (int j = 0; j < F1; j++) acc += ts[r][j] * W2s[j * F2 + m];
    g_h2[v * F2 + m] = acc * dv;
}

// ---------------------------------------------------------------------------
// Edge scatter layer 2: agg2[dst] += h2[src]   (16 floats = 4 lanes x float4)
// ---------------------------------------------------------------------------
__global__ void gcn_scatter2_kernel(const int* __restrict__ src,
                                    const int* __restrict__ dst) {
    int t = blockIdx.x * blockDim.x + threadIdx.x;
    int e = t >> 2;
    int lane = t & 3;
    if (e >= NEDGES) return;
    int s = src[e], d = dst[e];
    float4 v = *(const float4*)&g_h2[s * F2 + lane * 4];
    float* p = &g_agg2[d * F2 + lane * 4];
    asm volatile("red.global.add.v4.f32 [%0], {%1, %2, %3, %4};"
                 :: "l"(p), "f"(v.x), "f"(v.y), "f"(v.z), "f"(v.w) : "memory");
}

// ---------------------------------------------------------------------------
// Final: out = log_softmax(dinv*(agg2+h2) + b2)   (one thread per node)
// ---------------------------------------------------------------------------
__global__ void gcn_final_kernel(const float* __restrict__ b2,
                                 float* __restrict__ out) {
    int v = blockIdx.x * blockDim.x + threadIdx.x;
    if (v >= NNODES) return;
    float dv = g_dinv[v];
    float t[F2];
#pragma unroll
    for (int i = 0; i < 4; i++) {
        float4 a = *(const float4*)&g_agg2[v * F2 + i * 4];
        float4 h = *(const float4*)&g_h2 [v * F2 + i * 4];
        t[i * 4 + 0] = dv * (a.x + h.x) + b2[i * 4 + 0];
        t[i * 4 + 1] = dv * (a.y + h.y) + b2[i * 4 + 1];
        t[i * 4 + 2] = dv * (a.z + h.z) + b2[i * 4 + 2];
        t[i * 4 + 3] = dv * (a.w + h.w) + b2[i * 4 + 3];
    }
    float mx = t[0];
#pragma unroll
    for (int i = 1; i < F2; i++) mx = fmaxf(mx, t[i]);
    float s = 0.f;
#pragma unroll
    for (int i = 0; i < F2; i++) s += expf(t[i] - mx);
    float lse = mx + logf(s);
#pragma unroll
    for (int i = 0; i < 4; i++) {
        float4 o;
        o.x = t[i * 4 + 0] - lse;
        o.y = t[i * 4 + 1] - lse;
        o.z = t[i * 4 + 2] - lse;
        o.w = t[i * 4 + 3] - lse;
        *(float4*)&out[v * F2 + i * 4] = o;
    }
}

// ---------------------------------------------------------------------------
// Launch
// ---------------------------------------------------------------------------
extern "C" void kernel_launch(void* const* d_in, const int* in_sizes, int n_in,
                              void* d_out, int out_size) {
    const float* x  = (const float*)d_in[0];
    const int*   ei = (const int*)  d_in[1];
    const float* W1 = (const float*)d_in[2];
    const float* b1 = (const float*)d_in[3];
    const float* W2 = (const float*)d_in[4];
    const float* b2 = (const float*)d_in[5];
    float* out = (float*)d_out;

    const int* src = ei;
    const int* dst = ei + NEDGES;

    gcn_init_kernel   <<<(NNODES * F1 + 255) / 256, 256>>>();
    gcn_deg_kernel    <<<(NEDGES + 255) / 256, 256>>>(dst);
    gcn_dinv_kernel   <<<(NNODES + 255) / 256, 256>>>();
    gcn_gemm1_kernel  <<<NNODES / G1_ROWS, 256>>>(x, W1);
    gcn_scatter1_kernel<<<(NEDGES * 16) / 256, 256>>>(src, dst);
    gcn_layer2_kernel <<<NNODES / 16, 256>>>(W2, b1);
    gcn_scatter2_kernel<<<(NEDGES * 4) / 256, 256>>>(src, dst);
    gcn_final_kernel  <<<(NNODES + 255) / 256, 256>>>(b2, out);
}

// round 2
// speedup vs baseline: 1.2652x; 1.2652x over previous
#include <cuda_runtime.h>

#define NNODES 100000
#define NEDGES 1600000
#define F0 128
#define F1 64
#define F2 16

// Scratch (device globals: allocation-free, graph-safe)
__device__ float g_deg [NNODES];
__device__ float g_dinv[NNODES];
__device__ float g_h1  [NNODES * F1];
__device__ float g_agg1[NNODES * F1];
__device__ float g_h2  [NNODES * F2];
__device__ float g_agg2[NNODES * F2];

// ---------------------------------------------------------------------------
// f32x2 packed helpers (sm_103a FFMA2 — only reachable via PTX)
// ---------------------------------------------------------------------------
__device__ __forceinline__ unsigned long long pack2(float lo, float hi) {
    unsigned long long r;
    asm("mov.b64 %0, {%1, %2};" : "=l"(r) : "f"(lo), "f"(hi));
    return r;
}
__device__ __forceinline__ void unpack2(unsigned long long v, float& lo, float& hi) {
    asm("mov.b64 {%0, %1}, %2;" : "=f"(lo), "=f"(hi) : "l"(v));
}
__device__ __forceinline__ void fma2(unsigned long long& acc,
                                     unsigned long long a, unsigned long long b) {
    asm("fma.rn.f32x2 %0, %1, %2, %0;" : "+l"(acc) : "l"(a), "l"(b));
}
__device__ __forceinline__ unsigned long long mul2(unsigned long long a,
                                                   unsigned long long b) {
    unsigned long long r;
    asm("mul.rn.f32x2 %0, %1, %2;" : "=l"(r) : "l"(a), "l"(b));
    return r;
}

// ---------------------------------------------------------------------------
// Init: zero aggregation buffers, deg = 1 (self loop)
// ---------------------------------------------------------------------------
__global__ void gcn_init_kernel() {
    int i = blockIdx.x * blockDim.x + threadIdx.x;
    if (i < NNODES * F1) g_agg1[i] = 0.f;
    if (i < NNODES * F2) g_agg2[i] = 0.f;
    if (i < NNODES)      g_deg[i]  = 1.f;
}

// ---------------------------------------------------------------------------
// Degree accumulation over dst, then dinv = rsqrt(deg)
// ---------------------------------------------------------------------------
__global__ void gcn_deg_kernel(const int* __restrict__ dst) {
    int e = blockIdx.x * blockDim.x + threadIdx.x;
    if (e < NEDGES) atomicAdd(&g_deg[dst[e]], 1.0f);
}

__global__ void gcn_dinv_kernel() {
    int i = blockIdx.x * blockDim.x + threadIdx.x;
    if (i < NNODES) g_dinv[i] = rsqrtf(g_deg[i]);
}

// ---------------------------------------------------------------------------
// GEMM1: h1[v,:] = (x[v,:] @ W1) * dinv[v]     [N,128]x[128,64]
// Register-tiled 8x4 per thread, row-pairs packed into f32x2 (FFMA2).
// Block: 256 threads, BM=128 rows, full N=64, full K=128.
// ---------------------------------------------------------------------------
#define BM 128
#define XS_LD (F0 + 4)   // 132 floats per row: keeps float4 stores 16B-aligned
extern __shared__ float s_gemm1[];  // xs[BM][XS_LD] then Ws[F0][F1]

__global__ void __launch_bounds__(256, 2) gcn_gemm1_kernel(
        const float* __restrict__ x, const float* __restrict__ W1) {
    float* xs = s_gemm1;                 // BM * XS_LD
    float* Ws = s_gemm1 + BM * XS_LD;    // F0 * F1
    int tid = threadIdx.x;
    int row0 = blockIdx.x * BM;

    // Stage W1 (8192 floats), coalesced
    for (int i = tid; i < F0 * F1 / 4; i += 256)
        *(float4*)&Ws[i * 4] = *(const float4*)&W1[i * 4];

    // Stage x tile: i -> (row = i>>5, kq = i&31). Warp lanes share a row:
    // conflict-free 512B-contiguous stores, coalesced 512B global loads.
    for (int i = tid; i < BM * 32; i += 256) {
        int r = i >> 5, kq = i & 31;
        int v = row0 + r;
        float4 xv = (v < NNODES) ? *(const float4*)&x[v * F0 + kq * 4]
                                 : make_float4(0.f, 0.f, 0.f, 0.f);
        *(float4*)&xs[r * XS_LD + kq * 4] = xv;
    }
    __syncthreads();

    int ty = tid >> 4;          // 0..15 -> rows 8*ty .. 8*ty+7
    int tx = tid & 15;          // 0..15 -> cols 4*tx .. 4*tx+3
    const float* xrow = &xs[(ty * 8) * XS_LD];

    unsigned long long acc[4][4];   // [rowpair p][col c] : (row 2p, row 2p+1)
#pragma unroll
    for (int p = 0; p < 4; p++)
#pragma unroll
        for (int c = 0; c < 4; c++) acc[p][c] = 0ull;

#pragma unroll 4
    for (int k = 0; k < F0; k++) {
        unsigned long long px[4];
#pragma unroll
        for (int p = 0; p < 4; p++)
            px[p] = pack2(xrow[(2 * p) * XS_LD + k], xrow[(2 * p + 1) * XS_LD + k]);
        float4 w4 = *(const float4*)&Ws[k * F1 + tx * 4];
        unsigned long long pw[4];
        pw[0] = pack2(w4.x, w4.x); pw[1] = pack2(w4.y, w4.y);
        pw[2] = pack2(w4.z, w4.z); pw[3] = pack2(w4.w, w4.w);
#pragma unroll
        for (int p = 0; p < 4; p++)
#pragma unroll
            for (int c = 0; c < 4; c++) fma2(acc[p][c], px[p], pw[c]);
    }

    // Epilogue: scale row-pairs by dinv, store float4 per row
#pragma unroll
    for (int p = 0; p < 4; p++) {
        int v0 = row0 + ty * 8 + 2 * p;
        if (v0 >= NNODES) break;
        float d0 = g_dinv[v0];
        float d1 = (v0 + 1 < NNODES) ? g_dinv[v0 + 1] : 0.f;
        unsigned long long dd = pack2(d0, d1);
        float lo[4], hi[4];
#pragma unroll
        for (int c = 0; c < 4; c++) {
            unsigned long long s = mul2(acc[p][c], dd);
            unpack2(s, lo[c], hi[c]);
        }
        *(float4*)&g_h1[v0 * F1 + tx * 4] = make_float4(lo[0], lo[1], lo[2], lo[3]);
        if (v0 + 1 < NNODES)
            *(float4*)&g_h1[(v0 + 1) * F1 + tx * 4] = make_float4(hi[0], hi[1], hi[2], hi[3]);
    }
}

// ---------------------------------------------------------------------------
// Edge scatter layer 1: agg1[dst] += h1[src]   (64 floats = 16 lanes x float4)
// ---------------------------------------------------------------------------
__global__ void gcn_scatter1_kernel(const int* __restrict__ src,
                                    const int* __restrict__ dst) {
    int t = blockIdx.x * blockDim.x + threadIdx.x;
    int e = t >> 4;
    int lane = t & 15;
    if (e >= NEDGES) return;
    int s = src[e], d = dst[e];
    float4 v = *(const float4*)&g_h1[s * F1 + lane * 4];
    float* p = &g_agg1[d * F1 + lane * 4];
    asm volatile("red.global.add.v4.f32 [%0], {%1, %2, %3, %4};"
                 :: "l"(p), "f"(v.x), "f"(v.y), "f"(v.z), "f"(v.w) : "memory");
}

// ---------------------------------------------------------------------------
// Fused layer-2 input: t = leaky_relu(dinv*(agg1+h1) + b1); h2 = (t@W2)*dinv
// ---------------------------------------------------------------------------
__global__ void gcn_layer2_kernel(const float* __restrict__ W2,
                                  const float* __restrict__ b1) {
    __shared__ __align__(16) float W2s[F1 * F2];     // 4 KB
    __shared__ __align__(16) float ts[16][F1];       // 4 KB
    __shared__ float b1s[F1];
    int tid = threadIdx.x;
    for (int i = tid; i < F1 * F2; i += 256) W2s[i] = W2[i];
    if (tid < F1) b1s[tid] = b1[tid];
    __syncthreads();

    int r = tid >> 4;              // local node
    int m = tid & 15;              // output feature
    int v = blockIdx.x * 16 + r;
    float dv = g_dinv[v];

    {   // compute activated row t (4 features per thread)
        int j = m * 4;
        float4 a = *(const float4*)&g_agg1[v * F1 + j];
        float4 h = *(const float4*)&g_h1 [v * F1 + j];
        float4 t;
        t.x = dv * (a.x + h.x) + b1s[j + 0];
        t.y = dv * (a.y + h.y) + b1s[j + 1];
        t.z = dv * (a.z + h.z) + b1s[j + 2];
        t.w = dv * (a.w + h.w) + b1s[j + 3];
        t.x = t.x >= 0.f ? t.x : 0.2f * t.x;
        t.y = t.y >= 0.f ? t.y : 0.2f * t.y;
        t.z = t.z >= 0.f ? t.z : 0.2f * t.z;
        t.w = t.w >= 0.f ? t.w : 0.2f * t.w;
        *(float4*)&ts[r][j] = t;
    }
    __syncthreads();

    float acc = 0.f;
#pragma unroll
    for (int j = 0; j < F1; j++) acc += ts[r][j] * W2s[j * F2 + m];
    g_h2[v * F2 + m] = acc * dv;
}

// ---------------------------------------------------------------------------
// Edge scatter layer 2: agg2[dst] += h2[src]   (16 floats = 4 lanes x float4)
// ---------------------------------------------------------------------------
__global__ void gcn_scatter2_kernel(const int* __restrict__ src,
                                    const int* __restrict__ dst) {
    int t = blockIdx.x * blockDim.x + threadIdx.x;
    int e = t >> 2;
    int lane = t & 3;
    if (e >= NEDGES) return;
    int s = src[e], d = dst[e];
    float4 v = *(const float4*)&g_h2[s * F2 + lane * 4];
    float* p = &g_agg2[d * F2 + lane * 4];
    asm volatile("red.global.add.v4.f32 [%0], {%1, %2, %3, %4};"
                 :: "l"(p), "f"(v.x), "f"(v.y), "f"(v.z), "f"(v.w) : "memory");
}

// ---------------------------------------------------------------------------
// Final: out = log_softmax(dinv*(agg2+h2) + b2)   (one thread per node)
// ---------------------------------------------------------------------------
__global__ void gcn_final_kernel(const float* __restrict__ b2,
                                 float* __restrict__ out) {
    int v = blockIdx.x * blockDim.x + threadIdx.x;
    if (v >= NNODES) return;
    float dv = g_dinv[v];
    float t[F2];
#pragma unroll
    for (int i = 0; i < 4; i++) {
        float4 a = *(const float4*)&g_agg2[v * F2 + i * 4];
        float4 h = *(const float4*)&g_h2 [v * F2 + i * 4];
        t[i * 4 + 0] = dv * (a.x + h.x) + b2[i * 4 + 0];
        t[i * 4 + 1] = dv * (a.y + h.y) + b2[i * 4 + 1];
        t[i * 4 + 2] = dv * (a.z + h.z) + b2[i * 4 + 2];
        t[i * 4 + 3] = dv * (a.w + h.w) + b2[i * 4 + 3];
    }
    float mx = t[0];
#pragma unroll
    for (int i = 1; i < F2; i++) mx = fmaxf(mx, t[i]);
    float s = 0.f;
#pragma unroll
    for (int i = 0; i < F2; i++) s += expf(t[i] - mx);
    float lse = mx + logf(s);
#pragma unroll
    for (int i = 0; i < 4; i++) {
        float4 o;
        o.x = t[i * 4 + 0] - lse;
        o.y = t[i * 4 + 1] - lse;
        o.z = t[i * 4 + 2] - lse;
        o.w = t[i * 4 + 3] - lse;
        *(float4*)&out[v * F2 + i * 4] = o;
    }
}

// ---------------------------------------------------------------------------
// Launch
// ---------------------------------------------------------------------------
extern "C" void kernel_launch(void* const* d_in, const int* in_sizes, int n_in,
                              void* d_out, int out_size) {
    const float* x  = (const float*)d_in[0];
    const int*   ei = (const int*)  d_in[1];
    const float* W1 = (const float*)d_in[2];
    const float* b1 = (const float*)d_in[3];
    const float* W2 = (const float*)d_in[4];
    const float* b2 = (const float*)d_in[5];
    float* out = (float*)d_out;

    const int* src = ei;
    const int* dst = ei + NEDGES;

    const int gemm1_smem = (BM * XS_LD + F0 * F1) * (int)sizeof(float);  // ~100 KB
    cudaFuncSetAttribute(gcn_gemm1_kernel,
                         cudaFuncAttributeMaxDynamicSharedMemorySize, gemm1_smem);

    gcn_init_kernel    <<<(NNODES * F1 + 255) / 256, 256>>>();
    gcn_deg_kernel     <<<(NEDGES + 255) / 256, 256>>>(dst);
    gcn_dinv_kernel    <<<(NNODES + 255) / 256, 256>>>();
    gcn_gemm1_kernel   <<<(NNODES + BM - 1) / BM, 256, gemm1_smem>>>(x, W1);
    gcn_scatter1_kernel<<<(NEDGES * 16) / 256, 256>>>(src, dst);
    gcn_layer2_kernel  <<<NNODES / 16, 256>>>(W2, b1);
    gcn_scatter2_kernel<<<(NEDGES * 4) / 256, 256>>>(src, dst);
    gcn_final_kernel   <<<(NNODES + 255) / 256, 256>>>(b2, out);
}